// round 12
// baseline (speedup 1.0000x reference)
#include <cuda_runtime.h>
#include <cstdint>

// Fixed shapes
#define B_   2
#define T_   12
#define N_   10000
#define CG   16
#define CI   8
#define HW   16384
#define F_   64
#define FH   32
#define NPIX (B_*T_*HW)        // 393216
#define TILE 256               // stats tile (pixels per block)
#define SMS  260               // stats smem row stride (words)
#define NSTAT (NPIX/TILE)      // 1536
#define PXT  4                 // k_norm pixels per thread
#define NORM_TPB 256
#define NORM_TILE (NORM_TPB*PXT)       // 1024 px per block
#define NNORM (NPIX/NORM_TILE)         // 384
#define ZBLK 1024              // k_zero grid
#define MOMB ((NPIX/4)/256)    // 384 moment-active blocks in k_zero
#define BN_EPS 1e-5f

typedef unsigned long long ull;

// Scratch (no cudaMalloc allowed). interp layout [b,t,hw,c] (proven R8 layout).
__device__ __align__(128) float g_interp[(size_t)B_*T_*HW*CG]; // ~25MB
__device__ float g_sum[F_];            // graph channels use [0..31]
__device__ float g_sumsq[F_];
__device__ float g_part[44 * ZBLK];    // per-block moment partials [entry][block]
__device__ float g_S[8];               // Σ grid[c]
__device__ float g_M[36];              // Σ grid[c1]*grid[c2], upper tri

#define PACK2(d, lo, hi)   asm("mov.b64 %0, {%1, %2};" : "=l"(d) : "f"(lo), "f"(hi))
#define UNPACK2(lo, hi, s) asm("mov.b64 {%0, %1}, %2;" : "=f"(lo), "=f"(hi) : "l"(s))
#define FMA2(d, a, b, c)   asm("fma.rn.f32x2 %0, %1, %2, %3;" : "=l"(d) : "l"(a), "l"(b), "l"(c))
#define ADD2(d, a, b)      asm("add.rn.f32x2 %0, %1, %2;"     : "=l"(d) : "l"(a), "l"(b))
#define MUL2(d, a, b)      asm("mul.rn.f32x2 %0, %1, %2;"     : "=l"(d) : "l"(a), "l"(b))

// ---------------- K0: zero interp + grid-channel moment partials ----------------
__global__ void __launch_bounds__(256) k_zero(const float* __restrict__ grid_data) {
    const int tid = threadIdx.x;

    // phase A: zero interp (25MB; also warms L2 for the scatter atomics)
    {
        const size_t n4 = ((size_t)B_*T_*HW*CG) / 4;
        float4* p = (float4*)g_interp;
        const float4 z = make_float4(0.f, 0.f, 0.f, 0.f);
        for (size_t i = (size_t)blockIdx.x * 256 + tid; i < n4; i += (size_t)ZBLK * 256)
            p[i] = z;
        if (blockIdx.x == 0 && tid < F_) { g_sum[tid] = 0.f; g_sumsq[tid] = 0.f; }
    }

    // phase B: grid_data first+second moments. One 4-px quad per thread;
    // blocks [0, MOMB) active (exact partition). Partials: plain stores,
    // no pre-zero needed.
    if (blockIdx.x < MOMB) {
        int gid = blockIdx.x * 256 + tid;
        int P = gid * 4, bt = P >> 14, hw = P & (HW - 1);
        ull g01[CI], g23[CI];
#pragma unroll
        for (int c = 0; c < CI; c++) {
            float4 v = *(const float4*)&grid_data[((size_t)(bt * CI + c)) * HW + hw];
            PACK2(g01[c], v.x, v.y);
            PACK2(g23[c], v.z, v.w);
        }
        float vals[44];
#pragma unroll
        for (int c = 0; c < CI; c++) {
            ull s; ADD2(s, g01[c], g23[c]);
            float lo, hi; UNPACK2(lo, hi, s);
            vals[c] = lo + hi;
        }
        int k = 8;
#pragma unroll
        for (int c1 = 0; c1 < CI; c1++)
#pragma unroll
            for (int c2 = c1; c2 < CI; c2++) {
                ull m; MUL2(m, g01[c1], g01[c2]);
                FMA2(m, g23[c1], g23[c2], m);
                float lo, hi; UNPACK2(lo, hi, m);
                vals[k++] = lo + hi;
            }
        // warp reduce all 44
#pragma unroll
        for (int j = 0; j < 44; j++)
#pragma unroll
            for (int off = 16; off; off >>= 1)
                vals[j] += __shfl_down_sync(0xffffffffu, vals[j], off);

        __shared__ float red[44];
        if (tid < 44) red[tid] = 0.f;
        __syncthreads();
        if ((tid & 31) == 0)
#pragma unroll
            for (int j = 0; j < 44; j++) atomicAdd(&red[j], vals[j]);
        __syncthreads();
        if (tid < 44) g_part[tid * ZBLK + blockIdx.x] = red[tid];
    } else {
        if (tid < 44) g_part[tid * ZBLK + blockIdx.x] = 0.f;
    }
}

// ---------------- K1: scatter (+ block0 reduces moment partials) ----------------
// Grid is exactly B_*N_*CG / 256 blocks -> no bound check, no early return.
__global__ void k_scatter(const float* __restrict__ graph,
                          const float* __restrict__ coords) {
    const int tid = threadIdx.x;

    if (blockIdx.x == 0) {   // deterministic reduction of g_part -> g_S / g_M
        __shared__ float sw[8];
        for (int e = 0; e < 44; e++) {
            float v = 0.f;
#pragma unroll
            for (int i = 0; i < 4; i++) v += g_part[e * ZBLK + tid + i * 256];
#pragma unroll
            for (int off = 16; off; off >>= 1) v += __shfl_down_sync(0xffffffffu, v, off);
            if ((tid & 31) == 0) sw[tid >> 5] = v;
            __syncthreads();
            if (tid == 0) {
                float t = 0.f;
#pragma unroll
                for (int w = 0; w < 8; w++) t += sw[w];
                if (e < 8) g_S[e] = t; else g_M[e - 8] = t;
            }
            __syncthreads();
        }
    }

    int idx = blockIdx.x * 256 + tid;
    int c = idx & (CG - 1);
    int node = idx >> 4;
    int b = node / N_;
    int n = node - b * N_;

    float la = coords[(b * N_ + n) * 2 + 0];
    float lo = coords[(b * N_ + n) * 2 + 1];
    int lat = min(max((int)(la * 128.f), 0), 127);
    int lon = min(max((int)(lo * 128.f), 0), 127);
    int pos = lat * 128 + lon;

#pragma unroll
    for (int t = 0; t < T_; t++) {
        float v = graph[((size_t)(b * T_ + t) * N_ + n) * CG + c];
        atomicAdd(&g_interp[((size_t)(b * T_ + t) * HW + pos) * CG + c], v);
    }
}

// ---------------- K2: graph-channel stats only (25MB instead of 38MB) ----------------
__global__ void __launch_bounds__(256) k_stats(
    const float* __restrict__ Wg, const float* __restrict__ bg)
{
    __shared__ float s_in[CG * SMS];
    __shared__ float s_sum[FH], s_sq[FH];

    const int tid  = threadIdx.x;
    const int lane = tid & 31;
    const int warp = tid >> 5;
    const int P0   = blockIdx.x * TILE;

    if (tid < FH) { s_sum[tid] = 0.f; s_sq[tid] = 0.f; }

    // interp [px][c] -> s_in[c][px]
#pragma unroll
    for (int k = 0; k < 4; k++) {
        int q = tid + k * 256;
        float4 v = *(const float4*)&g_interp[(size_t)P0 * CG + q * 4];
        int pixel = q >> 2;
        int cq = (q & 3) * 4;
        s_in[(cq + 0) * SMS + pixel] = v.x;
        s_in[(cq + 1) * SMS + pixel] = v.y;
        s_in[(cq + 2) * SMS + pixel] = v.z;
        s_in[(cq + 3) * SMS + pixel] = v.w;
    }
    __syncthreads();

    ull wg2[CG], bg2;
#pragma unroll
    for (int c = 0; c < CG; c++) { float w = Wg[c * FH + lane]; PACK2(wg2[c], w, w); }
    { float x = bg[lane]; PACK2(bg2, x, x); }

    ull sum_g = 0, sq_g = 0;

    const int pbase = warp * 32;
#pragma unroll
    for (int g = 0; g < 8; g++) {
        const int p = pbase + g * 4;
        ull accg01 = bg2, accg23 = bg2;
#pragma unroll
        for (int c = 0; c < CG; c++) {
            ulonglong2 u = *(const ulonglong2*)&s_in[c * SMS + p];
            FMA2(accg01, u.x, wg2[c], accg01);
            FMA2(accg23, u.y, wg2[c], accg23);
        }
        ADD2(sum_g, sum_g, accg01); ADD2(sum_g, sum_g, accg23);
        FMA2(sq_g, accg01, accg01, sq_g); FMA2(sq_g, accg23, accg23, sq_g);
    }

    float lo, hi, a;
    UNPACK2(lo, hi, sum_g); a = lo + hi; atomicAdd(&s_sum[lane], a);
    UNPACK2(lo, hi, sq_g);  a = lo + hi; atomicAdd(&s_sq[lane], a);
    __syncthreads();
    if (tid < FH) {
        atomicAdd(&g_sum[tid],   s_sum[tid]);
        atomicAdd(&g_sumsq[tid], s_sq[tid]);
    }
}

// ---------------- K3: normalize + write (R7 body: unroll 4, lb(256,2)) ----------------
__global__ void __launch_bounds__(NORM_TPB, 2) k_norm(
    const float* __restrict__ grid_data,
    const float* __restrict__ Wg, const float* __restrict__ bg,
    const float* __restrict__ Wr, const float* __restrict__ br,
    const float* __restrict__ gamma, const float* __restrict__ beta,
    float* __restrict__ out)
{
    __shared__ float s_sc[F_], s_sh[F_];
    __shared__ __align__(16) ull s_wg[32 * 16]; // [f][c] dup-packed, scale-folded
    __shared__ __align__(16) ull s_wr[32 * 8];
    __shared__ ull s_fg[32], s_fr[32];          // fused bias+shift, dup-packed

    const int tid = threadIdx.x;
    const float inv = 1.0f / (float)NPIX;

    if (tid < 32) {                    // graph channels: accumulated sums
        float mean = g_sum[tid] * inv;
        float var  = g_sumsq[tid] * inv - mean * mean;
        float sc   = gamma[tid] * rsqrtf(var + BN_EPS);
        s_sc[tid] = sc;
        s_sh[tid] = beta[tid] - mean * sc;
    } else if (tid < 64) {             // grid channels: analytic from moments
        int j = tid - 32;
        float w[CI];
#pragma unroll
        for (int c = 0; c < CI; c++) w[c] = Wr[c * FH + j];
        float b = br[j];
        float sdot = 0.f;
#pragma unroll
        for (int c = 0; c < CI; c++) sdot += w[c] * g_S[c];
        float qsum = 0.f;
        int k = 0;
#pragma unroll
        for (int c1 = 0; c1 < CI; c1++) {
            qsum += w[c1] * w[c1] * g_M[k]; k++;
#pragma unroll
            for (int c2 = c1 + 1; c2 < CI; c2++) {
                qsum += 2.f * w[c1] * w[c2] * g_M[k]; k++;
            }
        }
        float sum_x = sdot + (float)NPIX * b;
        float sumsq = qsum + 2.f * b * sdot + (float)NPIX * b * b;
        float mean = sum_x * inv;
        float var  = sumsq * inv - mean * mean;
        float sc   = gamma[tid] * rsqrtf(var + BN_EPS);
        s_sc[tid] = sc;
        s_sh[tid] = beta[tid] - mean * sc;
    }
    __syncthreads();

    {
#pragma unroll
        for (int k = 0; k < 2; k++) {            // 512 graph weight entries
            int e = tid + k * 256;
            int f = e >> 4, c = e & 15;
            float w = Wg[c * FH + f] * s_sc[f];
            PACK2(s_wg[e], w, w);
        }
        {                                         // 256 grid weight entries
            int f = tid >> 3, c = tid & 7;
            float w = Wr[c * FH + f] * s_sc[32 + f];
            PACK2(s_wr[tid], w, w);
        }
        if (tid < 32) {
            float v = bg[tid] * s_sc[tid] + s_sh[tid];
            PACK2(s_fg[tid], v, v);
        } else if (tid < 64) {
            int f = tid - 32;
            float v = br[f] * s_sc[32 + f] + s_sh[32 + f];
            PACK2(s_fr[f], v, v);
        }
    }
    __syncthreads();

    const int P  = blockIdx.x * NORM_TILE + tid * PXT;   // first of 4 pixels
    const int bt = P >> 14;
    const int hw = P & (HW - 1);
    float* outp = out + (size_t)bt * F_ * HW + hw;

    // ---- graph half: 16 channels x 4 px as pixel-pair packs ----
    {
        ull a01[CG], a23[CG];
        const float4* ip = (const float4*)&g_interp[(size_t)P * CG];
#pragma unroll
        for (int k = 0; k < 4; k++) {
            float4 v0 = __ldcs(&ip[k]);        // px0, channels 4k..4k+3
            float4 v1 = __ldcs(&ip[4 + k]);    // px1
            float4 v2 = __ldcs(&ip[8 + k]);    // px2
            float4 v3 = __ldcs(&ip[12 + k]);   // px3
            PACK2(a01[4*k+0], v0.x, v1.x); PACK2(a23[4*k+0], v2.x, v3.x);
            PACK2(a01[4*k+1], v0.y, v1.y); PACK2(a23[4*k+1], v2.y, v3.y);
            PACK2(a01[4*k+2], v0.z, v1.z); PACK2(a23[4*k+2], v2.z, v3.z);
            PACK2(a01[4*k+3], v0.w, v1.w); PACK2(a23[4*k+3], v2.w, v3.w);
        }

#pragma unroll 4
        for (int f = 0; f < 32; f++) {
            ull acc01 = s_fg[f], acc23 = s_fg[f];
            const ulonglong2* wrow = (const ulonglong2*)&s_wg[f * 16];
#pragma unroll
            for (int cc = 0; cc < 8; cc++) {
                ulonglong2 w = wrow[cc];          // uniform -> broadcast
                FMA2(acc01, a01[2*cc],   w.x, acc01);
                FMA2(acc23, a23[2*cc],   w.x, acc23);
                FMA2(acc01, a01[2*cc+1], w.y, acc01);
                FMA2(acc23, a23[2*cc+1], w.y, acc23);
            }
            float4 o;
            UNPACK2(o.x, o.y, acc01);
            UNPACK2(o.z, o.w, acc23);
            __stcs((float4*)&outp[(size_t)f * HW], o);   // coalesced STG.128
        }
    }

    // ---- grid half: 8 channels x 4 px ----
    {
        ull g01[CI], g23[CI];
        const float* gp = &grid_data[(size_t)bt * CI * HW + hw];
#pragma unroll
        for (int c = 0; c < CI; c++) {
            float4 v = __ldcs((const float4*)&gp[(size_t)c * HW]);
            PACK2(g01[c], v.x, v.y);
            PACK2(g23[c], v.z, v.w);
        }

#pragma unroll 4
        for (int f = 0; f < 32; f++) {
            ull acc01 = s_fr[f], acc23 = s_fr[f];
            const ulonglong2* wrow = (const ulonglong2*)&s_wr[f * 8];
#pragma unroll
            for (int cc = 0; cc < 4; cc++) {
                ulonglong2 w = wrow[cc];
                FMA2(acc01, g01[2*cc],   w.x, acc01);
                FMA2(acc23, g23[2*cc],   w.x, acc23);
                FMA2(acc01, g01[2*cc+1], w.y, acc01);
                FMA2(acc23, g23[2*cc+1], w.y, acc23);
            }
            float4 o;
            UNPACK2(o.x, o.y, acc01);
            UNPACK2(o.z, o.w, acc23);
            __stcs((float4*)&outp[(size_t)(32 + f) * HW], o);
        }
    }
}

extern "C" void kernel_launch(void* const* d_in, const int* in_sizes, int n_in,
                              void* d_out, int out_size) {
    (void)in_sizes; (void)n_in; (void)out_size;
    const float* graph     = (const float*)d_in[0];
    const float* grid_data = (const float*)d_in[1];
    const float* coords    = (const float*)d_in[2];
    const float* Wg        = (const float*)d_in[5];
    const float* bg        = (const float*)d_in[6];
    const float* Wr        = (const float*)d_in[7];
    const float* br        = (const float*)d_in[8];
    const float* gamma     = (const float*)d_in[9];
    const float* beta      = (const float*)d_in[10];
    float* out = (float*)d_out;

    k_zero<<<ZBLK, 256>>>(grid_data);
    k_scatter<<<(B_ * N_ * CG) / 256, 256>>>(graph, coords);
    k_stats<<<NSTAT, 256>>>(Wg, bg);
    k_norm<<<NNORM, NORM_TPB>>>(grid_data, Wg, bg, Wr, br, gamma, beta, out);
}

// round 13
// speedup vs baseline: 1.1920x; 1.1920x over previous
#include <cuda_runtime.h>
#include <cstdint>

// Fixed shapes
#define B_   2
#define T_   12
#define N_   10000
#define CG   16
#define CI   8
#define HW   16384
#define F_   64
#define FH   32
#define NPIX (B_*T_*HW)        // 393216
#define TILE 256               // stats tile (pixels)
#define SMS  260               // stats smem row stride (words)
#define NSTAT (NPIX/TILE)      // 1536
#define PXT  4                 // norm pixels per thread
#define TPB  256
#define NTILE (TPB*PXT)        // 1024
#define NNORM (NPIX/NTILE)     // 384
#define BN_EPS 1e-5f

typedef unsigned long long ull;

// Scratch (no cudaMalloc allowed). interp layout [b,t,hw,c] (proven).
__device__ __align__(128) float g_interp[(size_t)B_*T_*HW*CG]; // ~25MB
__device__ float g_sum[F_];
__device__ float g_sumsq[F_];
__device__ unsigned int g_cnt = 0;   // barrier arrival counter
__device__ unsigned int g_gen = 0;   // barrier generation (monotonic across replays)

#define PACK2(d, lo, hi)   asm("mov.b64 %0, {%1, %2};" : "=l"(d) : "f"(lo), "f"(hi))
#define UNPACK2(lo, hi, s) asm("mov.b64 {%0, %1}, %2;" : "=f"(lo), "=f"(hi) : "l"(s))
#define FMA2(d, a, b, c)   asm("fma.rn.f32x2 %0, %1, %2, %3;" : "=l"(d) : "l"(a), "l"(b), "l"(c))
#define ADD2(d, a, b)      asm("add.rn.f32x2 %0, %1, %2;"     : "=l"(d) : "l"(a), "l"(b))

// Grid-wide barrier (R10-proven). All blocks resident by construction.
__device__ __forceinline__ void grid_barrier(unsigned int target) {
    __syncthreads();
    if (threadIdx.x == 0) {
        __threadfence();
        unsigned int a = atomicAdd(&g_cnt, 1u);
        if (a == gridDim.x - 1) {
            g_cnt = 0;
            __threadfence();
            atomicExch(&g_gen, target);          // release
        } else {
            unsigned int v;
            do {
                __nanosleep(64);
                asm volatile("ld.acquire.gpu.u32 %0, [%1];" : "=r"(v) : "l"(&g_gen));
            } while ((int)(v - target) < 0);
        }
    }
    __syncthreads();
}

// ---------------------------------------------------------------- K0: zero
// 25MB zero also warms L2 so scatter's atomics hit L2 (R8-proven effect).
__global__ void k_zero() {
    const size_t n4 = ((size_t)B_*T_*HW*CG) / 4;
    float4* p = (float4*)g_interp;
    const float4 z = make_float4(0.f, 0.f, 0.f, 0.f);
    for (size_t i = (size_t)blockIdx.x * blockDim.x + threadIdx.x; i < n4;
         i += (size_t)gridDim.x * blockDim.x)
        p[i] = z;
    if (blockIdx.x == 0 && threadIdx.x < F_) {
        g_sum[threadIdx.x] = 0.f;
        g_sumsq[threadIdx.x] = 0.f;
    }
}

// ------------------------------------------------------------- K1: scatter
__global__ void k_scatter(const float* __restrict__ graph,
                          const float* __restrict__ coords) {
    int idx = blockIdx.x * blockDim.x + threadIdx.x;   // grid exactly covers
    int c = idx & (CG - 1);
    int node = idx >> 4;
    int b = node / N_;
    int n = node - b * N_;

    float la = coords[(b * N_ + n) * 2 + 0];
    float lo = coords[(b * N_ + n) * 2 + 1];
    int lat = min(max((int)(la * 128.f), 0), 127);
    int lon = min(max((int)(lo * 128.f), 0), 127);
    int pos = lat * 128 + lon;

#pragma unroll
    for (int t = 0; t < T_; t++) {
        float v = graph[((size_t)(b * T_ + t) * N_ + n) * CG + c];
        atomicAdd(&g_interp[((size_t)(b * T_ + t) * HW + pos) * CG + c], v);
    }
}

// ------------------- K2: fused stats + grid-barrier + normalize -------------------
// Phase S = R8 stats body in a block-strided tile loop (lane = channel).
// Phase N = R7 norm body (4 px/thread, unroll 4) in a block-strided tile loop.
__global__ void __launch_bounds__(TPB, 2) k_sn(
    const float* __restrict__ grid_data,
    const float* __restrict__ Wg, const float* __restrict__ bg,
    const float* __restrict__ Wr, const float* __restrict__ br,
    const float* __restrict__ gamma, const float* __restrict__ beta,
    float* __restrict__ out)
{
    __shared__ union {
        float st[24 * SMS];                       // stats staging [c][px] (~25KB)
        struct {                                  // norm tables (~7.2KB)
            ull wg[32 * 16]; ull wr[32 * 8];
            ull fg[32]; ull fr[32];
            float sc[F_]; float sh[F_];
        } nm;
    } sm;
    __shared__ float s_sum[F_], s_sq[F_];

    const int tid  = threadIdx.x;
    const int lane = tid & 31;
    const int warp = tid >> 5;
    const int gsz  = gridDim.x;

    unsigned int bar_base = 0;
    if (tid == 0)
        asm volatile("ld.acquire.gpu.u32 %0, [%1];" : "=r"(bar_base) : "l"(&g_gen));

    // ================= phase S: BN statistics =================
    {
        if (tid < F_) { s_sum[tid] = 0.f; s_sq[tid] = 0.f; }

        ull wg2[CG], wr2[CI], bg2, br2;
#pragma unroll
        for (int c = 0; c < CG; c++) { float w = Wg[c * FH + lane]; PACK2(wg2[c], w, w); }
#pragma unroll
        for (int c = 0; c < CI; c++) { float w = Wr[c * FH + lane]; PACK2(wr2[c], w, w); }
        { float x = bg[lane]; PACK2(bg2, x, x); }
        { float x = br[lane]; PACK2(br2, x, x); }

        ull sum_g = 0, sq_g = 0, sum_r = 0, sq_r = 0;

        for (int tile = blockIdx.x; tile < NSTAT; tile += gsz) {
            const int P0  = tile * TILE;
            const int bt  = P0 >> 14;
            const int hw0 = P0 & (HW - 1);
            __syncthreads();                  // protect sm.st reuse across tiles
            // interp [px][c] -> sm.st[c][px]
#pragma unroll
            for (int k = 0; k < 4; k++) {
                int q = tid + k * 256;
                float4 v = *(const float4*)&g_interp[(size_t)P0 * CG + q * 4];
                int pixel = q >> 2;
                int cq = (q & 3) * 4;
                sm.st[(cq + 0) * SMS + pixel] = v.x;
                sm.st[(cq + 1) * SMS + pixel] = v.y;
                sm.st[(cq + 2) * SMS + pixel] = v.z;
                sm.st[(cq + 3) * SMS + pixel] = v.w;
            }
            // grid_data (channel-major) -> sm.st[16+c][px]
#pragma unroll
            for (int k = 0; k < 2; k++) {
                int qq = tid + k * 256;
                int c = qq >> 6;
                int p4 = (qq & 63) * 4;
                float4 v = *(const float4*)&grid_data[(size_t)(bt * CI + c) * HW + hw0 + p4];
                *(float4*)&sm.st[(16 + c) * SMS + p4] = v;
            }
            __syncthreads();

            const int pbase = warp * 32;
#pragma unroll
            for (int g = 0; g < 8; g++) {
                const int p = pbase + g * 4;
                ull accg01 = bg2, accg23 = bg2;
                ull accr01 = br2, accr23 = br2;
#pragma unroll
                for (int c = 0; c < CG; c++) {
                    ulonglong2 u = *(const ulonglong2*)&sm.st[c * SMS + p];
                    FMA2(accg01, u.x, wg2[c], accg01);
                    FMA2(accg23, u.y, wg2[c], accg23);
                }
#pragma unroll
                for (int c = 0; c < CI; c++) {
                    ulonglong2 u = *(const ulonglong2*)&sm.st[(16 + c) * SMS + p];
                    FMA2(accr01, u.x, wr2[c], accr01);
                    FMA2(accr23, u.y, wr2[c], accr23);
                }
                ADD2(sum_g, sum_g, accg01); ADD2(sum_g, sum_g, accg23);
                FMA2(sq_g, accg01, accg01, sq_g); FMA2(sq_g, accg23, accg23, sq_g);
                ADD2(sum_r, sum_r, accr01); ADD2(sum_r, sum_r, accr23);
                FMA2(sq_r, accr01, accr01, sq_r); FMA2(sq_r, accr23, accr23, sq_r);
            }
        }
        __syncthreads();
        float lo, hi, a;
        UNPACK2(lo, hi, sum_g); a = lo + hi; atomicAdd(&s_sum[lane], a);
        UNPACK2(lo, hi, sq_g);  a = lo + hi; atomicAdd(&s_sq[lane], a);
        UNPACK2(lo, hi, sum_r); a = lo + hi; atomicAdd(&s_sum[lane + 32], a);
        UNPACK2(lo, hi, sq_r);  a = lo + hi; atomicAdd(&s_sq[lane + 32], a);
        __syncthreads();
        if (tid < F_) {
            atomicAdd(&g_sum[tid],   s_sum[tid]);
            atomicAdd(&g_sumsq[tid], s_sq[tid]);
        }
    }

    grid_barrier(bar_base + 1);

    // ================= phase N: normalize + write (R7 body) =================
    {
        if (tid < F_) {
            const float inv = 1.0f / (float)NPIX;
            float mean = g_sum[tid] * inv;
            float var  = g_sumsq[tid] * inv - mean * mean;
            float sc   = gamma[tid] * rsqrtf(var + BN_EPS);
            sm.nm.sc[tid] = sc;
            sm.nm.sh[tid] = beta[tid] - mean * sc;
        }
        __syncthreads();
#pragma unroll
        for (int k = 0; k < 2; k++) {            // 512 graph weight entries
            int e = tid + k * 256;
            int f = e >> 4, c = e & 15;
            float w = Wg[c * FH + f] * sm.nm.sc[f];
            PACK2(sm.nm.wg[e], w, w);
        }
        {                                         // 256 grid weight entries
            int f = tid >> 3, c = tid & 7;
            float w = Wr[c * FH + f] * sm.nm.sc[32 + f];
            PACK2(sm.nm.wr[tid], w, w);
        }
        if (tid < 32) {
            float v = bg[tid] * sm.nm.sc[tid] + sm.nm.sh[tid];
            PACK2(sm.nm.fg[tid], v, v);
        } else if (tid < 64) {
            int f = tid - 32;
            float v = br[f] * sm.nm.sc[32 + f] + sm.nm.sh[32 + f];
            PACK2(sm.nm.fr[f], v, v);
        }
        __syncthreads();

        for (int tile = blockIdx.x; tile < NNORM; tile += gsz) {
            const int P  = tile * NTILE + tid * PXT;
            const int bt = P >> 14;
            const int hw = P & (HW - 1);
            float* outp = out + (size_t)bt * F_ * HW + hw;

            // graph half: 16 channels x 4 px as pixel-pair packs
            {
                ull a01[CG], a23[CG];
                const float4* ip = (const float4*)&g_interp[(size_t)P * CG];
#pragma unroll
                for (int k = 0; k < 4; k++) {
                    float4 v0 = ip[k];
                    float4 v1 = ip[4 + k];
                    float4 v2 = ip[8 + k];
                    float4 v3 = ip[12 + k];
                    PACK2(a01[4*k+0], v0.x, v1.x); PACK2(a23[4*k+0], v2.x, v3.x);
                    PACK2(a01[4*k+1], v0.y, v1.y); PACK2(a23[4*k+1], v2.y, v3.y);
                    PACK2(a01[4*k+2], v0.z, v1.z); PACK2(a23[4*k+2], v2.z, v3.z);
                    PACK2(a01[4*k+3], v0.w, v1.w); PACK2(a23[4*k+3], v2.w, v3.w);
                }
#pragma unroll 4
                for (int f = 0; f < 32; f++) {
                    ull acc01 = sm.nm.fg[f], acc23 = sm.nm.fg[f];
                    const ulonglong2* wrow = (const ulonglong2*)&sm.nm.wg[f * 16];
#pragma unroll
                    for (int cc = 0; cc < 8; cc++) {
                        ulonglong2 w = wrow[cc];              // uniform broadcast
                        FMA2(acc01, a01[2*cc],   w.x, acc01);
                        FMA2(acc23, a23[2*cc],   w.x, acc23);
                        FMA2(acc01, a01[2*cc+1], w.y, acc01);
                        FMA2(acc23, a23[2*cc+1], w.y, acc23);
                    }
                    float4 o;
                    UNPACK2(o.x, o.y, acc01);
                    UNPACK2(o.z, o.w, acc23);
                    *(float4*)&outp[(size_t)f * HW] = o;      // coalesced STG.128
                }
            }

            // grid half: 8 channels x 4 px
            {
                ull g01[CI], g23[CI];
                const float* gp = &grid_data[(size_t)bt * CI * HW + hw];
#pragma unroll
                for (int c = 0; c < CI; c++) {
                    float4 v = *(const float4*)&gp[(size_t)c * HW];
                    PACK2(g01[c], v.x, v.y);
                    PACK2(g23[c], v.z, v.w);
                }
#pragma unroll 4
                for (int f = 0; f < 32; f++) {
                    ull acc01 = sm.nm.fr[f], acc23 = sm.nm.fr[f];
                    const ulonglong2* wrow = (const ulonglong2*)&sm.nm.wr[f * 8];
#pragma unroll
                    for (int cc = 0; cc < 4; cc++) {
                        ulonglong2 w = wrow[cc];
                        FMA2(acc01, g01[2*cc],   w.x, acc01);
                        FMA2(acc23, g23[2*cc],   w.x, acc23);
                        FMA2(acc01, g01[2*cc+1], w.y, acc01);
                        FMA2(acc23, g23[2*cc+1], w.y, acc23);
                    }
                    float4 o;
                    UNPACK2(o.x, o.y, acc01);
                    UNPACK2(o.z, o.w, acc23);
                    *(float4*)&outp[(size_t)(32 + f) * HW] = o;
                }
            }
        }
    }
}

extern "C" void kernel_launch(void* const* d_in, const int* in_sizes, int n_in,
                              void* d_out, int out_size) {
    (void)in_sizes; (void)n_in; (void)out_size;
    const float* graph     = (const float*)d_in[0];
    const float* grid_data = (const float*)d_in[1];
    const float* coords    = (const float*)d_in[2];
    const float* Wg        = (const float*)d_in[5];
    const float* bg        = (const float*)d_in[6];
    const float* Wr        = (const float*)d_in[7];
    const float* br        = (const float*)d_in[8];
    const float* gamma     = (const float*)d_in[9];
    const float* beta      = (const float*)d_in[10];
    float* out = (float*)d_out;

    // Size fused grid so ALL blocks are simultaneously resident.
    int dev = 0;  cudaGetDevice(&dev);
    int nsm = 0;  cudaDeviceGetAttribute(&nsm, cudaDevAttrMultiProcessorCount, dev);
    int maxb = 0;
    cudaOccupancyMaxActiveBlocksPerMultiprocessor(&maxb, k_sn, TPB, 0);
    if (maxb < 1) maxb = 1;
    int nblk = nsm * maxb;

    k_zero<<<1024, 256>>>();
    k_scatter<<<(B_ * N_ * CG) / 256, 256>>>(graph, coords);
    k_sn<<<nblk, TPB>>>(grid_data, Wg, bg, Wr, br, gamma, beta, out);
}

// round 14
// speedup vs baseline: 1.3061x; 1.0957x over previous
#include <cuda_runtime.h>
#include <cstdint>

// Fixed shapes
#define B_   2
#define T_   12
#define N_   10000
#define CG   16
#define CI   8
#define HW   16384
#define F_   64
#define FH   32
#define NPIX (B_*T_*HW)        // 393216
#define TILE 256               // stats tile (pixels per block)
#define SMS  260               // stats smem row stride (words)
#define NSTAT (NPIX/TILE)      // 1536
#define PXT  4                 // k_norm pixels per thread
#define NORM_TPB 256
#define NORM_TILE (NORM_TPB*PXT)       // 1024 px per block
#define NNORM (NPIX/NORM_TILE)         // 384
#define SCB  ((B_*N_*CG)/256)  // 1250 scatter blocks
#define GMB  192               // grid-moment blocks (tail of k_scatter)
#define BN_EPS 1e-5f

typedef unsigned long long ull;

// Scratch (no cudaMalloc allowed). interp layout [b,t,hw,c] (proven).
__device__ __align__(128) float g_interp[(size_t)B_*T_*HW*CG]; // ~25MB
__device__ float g_sum[FH];       // graph-channel Σx
__device__ float g_sumsq[FH];     // graph-channel Σx²
__device__ float g_mom[44];       // grid_data moments: [0..7]=Σg_c, [8..43]=Σ g_c1·g_c2 (c1<=c2)

#define PACK2(d, lo, hi)   asm("mov.b64 %0, {%1, %2};" : "=l"(d) : "f"(lo), "f"(hi))
#define UNPACK2(lo, hi, s) asm("mov.b64 {%0, %1}, %2;" : "=f"(lo), "=f"(hi) : "l"(s))
#define FMA2(d, a, b, c)   asm("fma.rn.f32x2 %0, %1, %2, %3;" : "=l"(d) : "l"(a), "l"(b), "l"(c))
#define ADD2(d, a, b)      asm("add.rn.f32x2 %0, %1, %2;"     : "=l"(d) : "l"(a), "l"(b))

// ---------------------------------------------------------------- K0: zero
// 25MB zero also warms L2 so scatter's atomics hit L2 (R8-proven effect).
__global__ void k_zero() {
    const size_t n4 = ((size_t)B_*T_*HW*CG) / 4;
    float4* p = (float4*)g_interp;
    const float4 z = make_float4(0.f, 0.f, 0.f, 0.f);
    for (size_t i = (size_t)blockIdx.x * blockDim.x + threadIdx.x; i < n4;
         i += (size_t)gridDim.x * blockDim.x)
        p[i] = z;
    if (blockIdx.x == 0) {
        int t = threadIdx.x;
        if (t < FH)            { g_sum[t] = 0.f; g_sumsq[t] = 0.f; }
        else if (t < FH + 44)  { g_mom[t - FH] = 0.f; }
    }
}

// ------------------- K1: scatter + grid_data moments (independent roles) -------------------
// Blocks [0, SCB): scatter-add graph nodes into g_interp.
// Blocks [SCB, SCB+GMB): accumulate grid_data first/second moments into g_mom.
// The two roles share no data; they just share the launch (no extra node/gap).
__global__ void __launch_bounds__(256) k_scatter(const float* __restrict__ graph,
                                                 const float* __restrict__ coords,
                                                 const float* __restrict__ grid_data) {
    const int tid = threadIdx.x;

    if (blockIdx.x < SCB) {
        int idx = blockIdx.x * 256 + tid;          // exact cover: SCB*256 = B*N*CG
        int c = idx & (CG - 1);
        int node = idx >> 4;
        int b = node / N_;
        int n = node - b * N_;

        float la = coords[(b * N_ + n) * 2 + 0];
        float lo = coords[(b * N_ + n) * 2 + 1];
        int lat = min(max((int)(la * 128.f), 0), 127);
        int lon = min(max((int)(lo * 128.f), 0), 127);
        int pos = lat * 128 + lon;

#pragma unroll
        for (int t = 0; t < T_; t++) {
            float v = graph[((size_t)(b * T_ + t) * N_ + n) * CG + c];
            atomicAdd(&g_interp[((size_t)(b * T_ + t) * HW + pos) * CG + c], v);
        }
        return;
    }

    // ---- grid moments role ----
    const int gb = blockIdx.x - SCB;               // 0..GMB-1
    float S[CI] = {};
    float M[36] = {};

    // Each block owns 512 quads (2048 px); each thread 2 quads.
#pragma unroll
    for (int rep = 0; rep < 2; rep++) {
        int qi = gb * 512 + rep * 256 + tid;       // quad index, 4 px each
        int P  = qi * 4;
        int bt = P >> 14;
        int hw = P & (HW - 1);
        float4 vv[CI];
#pragma unroll
        for (int c = 0; c < CI; c++)
            vv[c] = *(const float4*)&grid_data[((size_t)(bt * CI + c)) * HW + hw];
        int k = 0;
#pragma unroll
        for (int c1 = 0; c1 < CI; c1++) {
            S[c1] += (vv[c1].x + vv[c1].y) + (vv[c1].z + vv[c1].w);
#pragma unroll
            for (int c2 = c1; c2 < CI; c2++) {
                M[k] += vv[c1].x * vv[c2].x + vv[c1].y * vv[c2].y
                      + vv[c1].z * vv[c2].z + vv[c1].w * vv[c2].w;
                k++;
            }
        }
    }

    // warp-reduce all 44, then smem, then 44 global atomics per block
    __shared__ float red[44];
    if (tid < 44) red[tid] = 0.f;
    __syncthreads();
#pragma unroll
    for (int j = 0; j < CI; j++)
#pragma unroll
        for (int off = 16; off; off >>= 1) S[j] += __shfl_down_sync(0xffffffffu, S[j], off);
#pragma unroll
    for (int j = 0; j < 36; j++)
#pragma unroll
        for (int off = 16; off; off >>= 1) M[j] += __shfl_down_sync(0xffffffffu, M[j], off);
    if ((tid & 31) == 0) {
#pragma unroll
        for (int j = 0; j < CI; j++) atomicAdd(&red[j], S[j]);
#pragma unroll
        for (int j = 0; j < 36; j++) atomicAdd(&red[CI + j], M[j]);
    }
    __syncthreads();
    if (tid < 44) atomicAdd(&g_mom[tid], red[tid]);
}

// ---------------- K2: graph-channel stats only (25MB instead of 38MB) ----------------
__global__ void __launch_bounds__(256) k_stats(
    const float* __restrict__ Wg, const float* __restrict__ bg)
{
    __shared__ float s_in[CG * SMS];
    __shared__ float s_sum[FH], s_sq[FH];

    const int tid  = threadIdx.x;
    const int lane = tid & 31;
    const int warp = tid >> 5;
    const int P0   = blockIdx.x * TILE;

    if (tid < FH) { s_sum[tid] = 0.f; s_sq[tid] = 0.f; }

    // interp [px][c] -> s_in[c][px]
#pragma unroll
    for (int k = 0; k < 4; k++) {
        int q = tid + k * 256;
        float4 v = *(const float4*)&g_interp[(size_t)P0 * CG + q * 4];
        int pixel = q >> 2;
        int cq = (q & 3) * 4;
        s_in[(cq + 0) * SMS + pixel] = v.x;
        s_in[(cq + 1) * SMS + pixel] = v.y;
        s_in[(cq + 2) * SMS + pixel] = v.z;
        s_in[(cq + 3) * SMS + pixel] = v.w;
    }
    __syncthreads();

    ull wg2[CG], bg2;
#pragma unroll
    for (int c = 0; c < CG; c++) { float w = Wg[c * FH + lane]; PACK2(wg2[c], w, w); }
    { float x = bg[lane]; PACK2(bg2, x, x); }

    ull sum_g = 0, sq_g = 0;

    const int pbase = warp * 32;
#pragma unroll
    for (int g = 0; g < 8; g++) {
        const int p = pbase + g * 4;
        ull accg01 = bg2, accg23 = bg2;
#pragma unroll
        for (int c = 0; c < CG; c++) {
            ulonglong2 u = *(const ulonglong2*)&s_in[c * SMS + p];
            FMA2(accg01, u.x, wg2[c], accg01);
            FMA2(accg23, u.y, wg2[c], accg23);
        }
        ADD2(sum_g, sum_g, accg01); ADD2(sum_g, sum_g, accg23);
        FMA2(sq_g, accg01, accg01, sq_g); FMA2(sq_g, accg23, accg23, sq_g);
    }

    float lo, hi, a;
    UNPACK2(lo, hi, sum_g); a = lo + hi; atomicAdd(&s_sum[lane], a);
    UNPACK2(lo, hi, sq_g);  a = lo + hi; atomicAdd(&s_sq[lane], a);
    __syncthreads();
    if (tid < FH) {
        atomicAdd(&g_sum[tid],   s_sum[tid]);
        atomicAdd(&g_sumsq[tid], s_sq[tid]);
    }
}

// ---------------- K3: normalize + write (R7 body; analytic grid-side BN) ----------------
__global__ void __launch_bounds__(NORM_TPB, 2) k_norm(
    const float* __restrict__ grid_data,
    const float* __restrict__ Wg, const float* __restrict__ bg,
    const float* __restrict__ Wr, const float* __restrict__ br,
    const float* __restrict__ gamma, const float* __restrict__ beta,
    float* __restrict__ out)
{
    __shared__ float s_sc[F_], s_sh[F_];
    __shared__ __align__(16) ull s_wg[32 * 16]; // [f][c] dup-packed, scale-folded
    __shared__ __align__(16) ull s_wr[32 * 8];
    __shared__ ull s_fg[32], s_fr[32];          // fused bias+shift, dup-packed

    const int tid = threadIdx.x;
    const float inv = 1.0f / (float)NPIX;

    if (tid < 32) {                    // graph channels: accumulated sums
        float mean = g_sum[tid] * inv;
        float var  = g_sumsq[tid] * inv - mean * mean;
        float sc   = gamma[tid] * rsqrtf(var + BN_EPS);
        s_sc[tid] = sc;
        s_sh[tid] = beta[tid] - mean * sc;
    } else if (tid < 64) {             // grid channels: analytic from moments (R12-validated)
        int j = tid - 32;
        float w[CI];
#pragma unroll
        for (int c = 0; c < CI; c++) w[c] = Wr[c * FH + j];
        float b = br[j];
        float sdot = 0.f;
#pragma unroll
        for (int c = 0; c < CI; c++) sdot += w[c] * g_mom[c];
        float qsum = 0.f;
        int k = 0;
#pragma unroll
        for (int c1 = 0; c1 < CI; c1++) {
            qsum += w[c1] * w[c1] * g_mom[CI + k]; k++;
#pragma unroll
            for (int c2 = c1 + 1; c2 < CI; c2++) {
                qsum += 2.f * w[c1] * w[c2] * g_mom[CI + k]; k++;
            }
        }
        float sum_x = sdot + (float)NPIX * b;
        float sumsq = qsum + 2.f * b * sdot + (float)NPIX * b * b;
        float mean = sum_x * inv;
        float var  = sumsq * inv - mean * mean;
        float sc   = gamma[tid] * rsqrtf(var + BN_EPS);
        s_sc[tid] = sc;
        s_sh[tid] = beta[tid] - mean * sc;
    }
    __syncthreads();

    {
#pragma unroll
        for (int k = 0; k < 2; k++) {            // 512 graph weight entries
            int e = tid + k * 256;
            int f = e >> 4, c = e & 15;
            float w = Wg[c * FH + f] * s_sc[f];
            PACK2(s_wg[e], w, w);
        }
        {                                         // 256 grid weight entries
            int f = tid >> 3, c = tid & 7;
            float w = Wr[c * FH + f] * s_sc[32 + f];
            PACK2(s_wr[tid], w, w);
        }
        if (tid < 32) {
            float v = bg[tid] * s_sc[tid] + s_sh[tid];
            PACK2(s_fg[tid], v, v);
        } else if (tid < 64) {
            int f = tid - 32;
            float v = br[f] * s_sc[32 + f] + s_sh[32 + f];
            PACK2(s_fr[f], v, v);
        }
    }
    __syncthreads();

    const int P  = blockIdx.x * NORM_TILE + tid * PXT;   // first of 4 pixels
    const int bt = P >> 14;
    const int hw = P & (HW - 1);
    float* outp = out + (size_t)bt * F_ * HW + hw;

    // ---- graph half: 16 channels x 4 px as pixel-pair packs ----
    {
        ull a01[CG], a23[CG];
        const float4* ip = (const float4*)&g_interp[(size_t)P * CG];
#pragma unroll
        for (int k = 0; k < 4; k++) {
            float4 v0 = __ldcs(&ip[k]);        // px0, channels 4k..4k+3
            float4 v1 = __ldcs(&ip[4 + k]);    // px1
            float4 v2 = __ldcs(&ip[8 + k]);    // px2
            float4 v3 = __ldcs(&ip[12 + k]);   // px3
            PACK2(a01[4*k+0], v0.x, v1.x); PACK2(a23[4*k+0], v2.x, v3.x);
            PACK2(a01[4*k+1], v0.y, v1.y); PACK2(a23[4*k+1], v2.y, v3.y);
            PACK2(a01[4*k+2], v0.z, v1.z); PACK2(a23[4*k+2], v2.z, v3.z);
            PACK2(a01[4*k+3], v0.w, v1.w); PACK2(a23[4*k+3], v2.w, v3.w);
        }

#pragma unroll 4
        for (int f = 0; f < 32; f++) {
            ull acc01 = s_fg[f], acc23 = s_fg[f];
            const ulonglong2* wrow = (const ulonglong2*)&s_wg[f * 16];
#pragma unroll
            for (int cc = 0; cc < 8; cc++) {
                ulonglong2 w = wrow[cc];          // uniform -> broadcast
                FMA2(acc01, a01[2*cc],   w.x, acc01);
                FMA2(acc23, a23[2*cc],   w.x, acc23);
                FMA2(acc01, a01[2*cc+1], w.y, acc01);
                FMA2(acc23, a23[2*cc+1], w.y, acc23);
            }
            float4 o;
            UNPACK2(o.x, o.y, acc01);
            UNPACK2(o.z, o.w, acc23);
            __stcs((float4*)&outp[(size_t)f * HW], o);   // coalesced STG.128
        }
    }

    // ---- grid half: 8 channels x 4 px ----
    {
        ull g01[CI], g23[CI];
        const float* gp = &grid_data[(size_t)bt * CI * HW + hw];
#pragma unroll
        for (int c = 0; c < CI; c++) {
            float4 v = __ldcs((const float4*)&gp[(size_t)c * HW]);
            PACK2(g01[c], v.x, v.y);
            PACK2(g23[c], v.z, v.w);
        }

#pragma unroll 4
        for (int f = 0; f < 32; f++) {
            ull acc01 = s_fr[f], acc23 = s_fr[f];
            const ulonglong2* wrow = (const ulonglong2*)&s_wr[f * 8];
#pragma unroll
            for (int cc = 0; cc < 4; cc++) {
                ulonglong2 w = wrow[cc];
                FMA2(acc01, g01[2*cc],   w.x, acc01);
                FMA2(acc23, g23[2*cc],   w.x, acc23);
                FMA2(acc01, g01[2*cc+1], w.y, acc01);
                FMA2(acc23, g23[2*cc+1], w.y, acc23);
            }
            float4 o;
            UNPACK2(o.x, o.y, acc01);
            UNPACK2(o.z, o.w, acc23);
            __stcs((float4*)&outp[(size_t)(32 + f) * HW], o);
        }
    }
}

extern "C" void kernel_launch(void* const* d_in, const int* in_sizes, int n_in,
                              void* d_out, int out_size) {
    (void)in_sizes; (void)n_in; (void)out_size;
    const float* graph     = (const float*)d_in[0];
    const float* grid_data = (const float*)d_in[1];
    const float* coords    = (const float*)d_in[2];
    const float* Wg        = (const float*)d_in[5];
    const float* bg        = (const float*)d_in[6];
    const float* Wr        = (const float*)d_in[7];
    const float* br        = (const float*)d_in[8];
    const float* gamma     = (const float*)d_in[9];
    const float* beta      = (const float*)d_in[10];
    float* out = (float*)d_out;

    k_zero<<<1024, 256>>>();
    k_scatter<<<SCB + GMB, 256>>>(graph, coords, grid_data);
    k_stats<<<NSTAT, 256>>>(Wg, bg);
    k_norm<<<NNORM, NORM_TPB>>>(grid_data, Wg, bg, Wr, br, gamma, beta, out);
}

// round 16
// speedup vs baseline: 1.3125x; 1.0049x over previous
#include <cuda_runtime.h>
#include <cstdint>

// Fixed shapes
#define B_   2
#define T_   12
#define N_   10000
#define CG   16
#define CI   8
#define HW   16384
#define F_   64
#define FH   32
#define NPIX (B_*T_*HW)        // 393216
#define TILE 256               // stats tile (pixels per block)
#define SMS  260               // stats smem row stride (words)
#define NSTAT (NPIX/TILE)      // 1536
#define PXT  4                 // k_norm pixels per thread
#define NORM_TPB 256
#define NORM_TILE (NORM_TPB*PXT)       // 1024 px per block
#define NNORM (NPIX/NORM_TILE)         // 384
#define SCB  ((B_*N_*CG)/256)  // 1250 scatter blocks
#define GMB  192               // grid-moment blocks (tail of k_scatter)
#define BN_EPS 1e-5f

typedef unsigned long long ull;

// Scratch (no cudaMalloc allowed). interp layout [b,t,hw,c] (proven).
__device__ __align__(128) float g_interp[(size_t)B_*T_*HW*CG]; // ~25MB
__device__ float g_sum[FH];       // graph-channel Σx
__device__ float g_sumsq[FH];     // graph-channel Σx²
__device__ float g_mom[44];       // grid moments: [0..7]=Σg_c, [8..43]=Σ g_c1 g_c2 (c1<=c2)

#define PACK2(d, lo, hi)   asm("mov.b64 %0, {%1, %2};" : "=l"(d) : "f"(lo), "f"(hi))
#define UNPACK2(lo, hi, s) asm("mov.b64 {%0, %1}, %2;" : "=f"(lo), "=f"(hi) : "l"(s))
#define FMA2(d, a, b, c)   asm("fma.rn.f32x2 %0, %1, %2, %3;" : "=l"(d) : "l"(a), "l"(b), "l"(c))
#define ADD2(d, a, b)      asm("add.rn.f32x2 %0, %1, %2;"     : "=l"(d) : "l"(a), "l"(b))

// PDL: trigger early launch of the stream-dependent kernel; wait for the
// predecessor's memory to be visible before touching data it wrote.
#define PDL_TRIGGER() asm volatile("griddepcontrol.launch_dependents;" ::: "memory")
#define PDL_WAIT()    asm volatile("griddepcontrol.wait;" ::: "memory")

// ---------------------------------------------------------------- K0: zero
// 25MB zero also warms L2 so scatter's atomics hit L2 (R8-proven effect).
__global__ void k_zero() {
    PDL_TRIGGER();                 // let scatter launch + do its input reads now
    const size_t n4 = ((size_t)B_*T_*HW*CG) / 4;
    float4* p = (float4*)g_interp;
    const float4 z = make_float4(0.f, 0.f, 0.f, 0.f);
    for (size_t i = (size_t)blockIdx.x * blockDim.x + threadIdx.x; i < n4;
         i += (size_t)gridDim.x * blockDim.x)
        p[i] = z;
    if (blockIdx.x == 0) {
        int t = threadIdx.x;
        if (t < FH)            { g_sum[t] = 0.f; g_sumsq[t] = 0.f; }
        else if (t < FH + 44)  { g_mom[t - FH] = 0.f; }
    }
}

// ------------------- K1: scatter + grid_data moments -------------------
// Blocks [0, SCB): scatter-add graph nodes. Blocks [SCB, SCB+GMB): grid moments.
// PDL: all input reads happen BEFORE the wait (overlap with k_zero); only the
// atomics (which touch zero-initialized buffers) sit after it.
__global__ void __launch_bounds__(256) k_scatter(const float* __restrict__ graph,
                                                 const float* __restrict__ coords,
                                                 const float* __restrict__ grid_data) {
    PDL_TRIGGER();                 // let stats launch + pack weights now
    const int tid = threadIdx.x;

    if (blockIdx.x < SCB) {
        int idx = blockIdx.x * 256 + tid;          // exact cover: SCB*256 = B*N*CG
        int c = idx & (CG - 1);
        int node = idx >> 4;
        int b = node / N_;
        int n = node - b * N_;

        float la = coords[(b * N_ + n) * 2 + 0];
        float lo = coords[(b * N_ + n) * 2 + 1];
        int lat = min(max((int)(la * 128.f), 0), 127);
        int lon = min(max((int)(lo * 128.f), 0), 127);
        int pos = lat * 128 + lon;

        float v[T_];
#pragma unroll
        for (int t = 0; t < T_; t++)               // pure input reads — pre-wait
            v[t] = graph[((size_t)(b * T_ + t) * N_ + n) * CG + c];

        PDL_WAIT();                                // zero must be complete
#pragma unroll
        for (int t = 0; t < T_; t++)
            atomicAdd(&g_interp[((size_t)(b * T_ + t) * HW + pos) * CG + c], v[t]);
        return;
    }

    // ---- grid moments role (reads only grid_data: pre-wait safe) ----
    const int gb = blockIdx.x - SCB;               // 0..GMB-1
    float S[CI] = {};
    float M[36] = {};
#pragma unroll
    for (int rep = 0; rep < 2; rep++) {
        int qi = gb * 512 + rep * 256 + tid;       // quad index, 4 px each
        int P  = qi * 4;
        int bt = P >> 14;
        int hw = P & (HW - 1);
        float4 vv[CI];
#pragma unroll
        for (int c = 0; c < CI; c++)
            vv[c] = *(const float4*)&grid_data[((size_t)(bt * CI + c)) * HW + hw];
        int k = 0;
#pragma unroll
        for (int c1 = 0; c1 < CI; c1++) {
            S[c1] += (vv[c1].x + vv[c1].y) + (vv[c1].z + vv[c1].w);
#pragma unroll
            for (int c2 = c1; c2 < CI; c2++) {
                M[k] += vv[c1].x * vv[c2].x + vv[c1].y * vv[c2].y
                      + vv[c1].z * vv[c2].z + vv[c1].w * vv[c2].w;
                k++;
            }
        }
    }

    __shared__ float red[44];
    if (tid < 44) red[tid] = 0.f;
    __syncthreads();
#pragma unroll
    for (int j = 0; j < CI; j++)
#pragma unroll
        for (int off = 16; off; off >>= 1) S[j] += __shfl_down_sync(0xffffffffu, S[j], off);
#pragma unroll
    for (int j = 0; j < 36; j++)
#pragma unroll
        for (int off = 16; off; off >>= 1) M[j] += __shfl_down_sync(0xffffffffu, M[j], off);
    if ((tid & 31) == 0) {
#pragma unroll
        for (int j = 0; j < CI; j++) atomicAdd(&red[j], S[j]);
#pragma unroll
        for (int j = 0; j < 36; j++) atomicAdd(&red[CI + j], M[j]);
    }
    __syncthreads();
    PDL_WAIT();                                    // g_mom zeroed by k_zero
    if (tid < 44) atomicAdd(&g_mom[tid], red[tid]);
}

// ---------------- K2: graph-channel stats only (interp, 25MB) ----------------
__global__ void __launch_bounds__(256) k_stats(
    const float* __restrict__ Wg, const float* __restrict__ bg)
{
    __shared__ float s_in[CG * SMS];
    __shared__ float s_sum[FH], s_sq[FH];

    PDL_TRIGGER();                 // let norm launch now
    const int tid  = threadIdx.x;
    const int lane = tid & 31;
    const int warp = tid >> 5;
    const int P0   = blockIdx.x * TILE;

    if (tid < FH) { s_sum[tid] = 0.f; s_sq[tid] = 0.f; }

    // weight setup: reads only Wg/bg — pre-wait (overlaps scatter's tail)
    ull wg2[CG], bg2;
#pragma unroll
    for (int c = 0; c < CG; c++) { float w = Wg[c * FH + lane]; PACK2(wg2[c], w, w); }
    { float x = bg[lane]; PACK2(bg2, x, x); }

    PDL_WAIT();                    // scatter's atomics must be visible

    // interp [px][c] -> s_in[c][px]
#pragma unroll
    for (int k = 0; k < 4; k++) {
        int q = tid + k * 256;
        float4 v = *(const float4*)&g_interp[(size_t)P0 * CG + q * 4];
        int pixel = q >> 2;
        int cq = (q & 3) * 4;
        s_in[(cq + 0) * SMS + pixel] = v.x;
        s_in[(cq + 1) * SMS + pixel] = v.y;
        s_in[(cq + 2) * SMS + pixel] = v.z;
        s_in[(cq + 3) * SMS + pixel] = v.w;
    }
    __syncthreads();

    ull sum_g = 0, sq_g = 0;

    const int pbase = warp * 32;
#pragma unroll
    for (int g = 0; g < 8; g++) {
        const int p = pbase + g * 4;
        ull accg01 = bg2, accg23 = bg2;
#pragma unroll
        for (int c = 0; c < CG; c++) {
            ulonglong2 u = *(const ulonglong2*)&s_in[c * SMS + p];
            FMA2(accg01, u.x, wg2[c], accg01);
            FMA2(accg23, u.y, wg2[c], accg23);
        }
        ADD2(sum_g, sum_g, accg01); ADD2(sum_g, sum_g, accg23);
        FMA2(sq_g, accg01, accg01, sq_g); FMA2(sq_g, accg23, accg23, sq_g);
    }

    float lo, hi, a;
    UNPACK2(lo, hi, sum_g); a = lo + hi; atomicAdd(&s_sum[lane], a);
    UNPACK2(lo, hi, sq_g);  a = lo + hi; atomicAdd(&s_sq[lane], a);
    __syncthreads();
    if (tid < FH) {
        atomicAdd(&g_sum[tid],   s_sum[tid]);
        atomicAdd(&g_sumsq[tid], s_sq[tid]);
    }
}

// ---------------- K3: normalize + write (R7 body; analytic grid-side BN) ----------------
__global__ void __launch_bounds__(NORM_TPB, 2) k_norm(
    const float* __restrict__ grid_data,
    const float* __restrict__ Wg, const float* __restrict__ bg,
    const float* __restrict__ Wr, const float* __restrict__ br,
    const float* __restrict__ gamma, const float* __restrict__ beta,
    float* __restrict__ out)
{
    __shared__ float s_sc[F_], s_sh[F_];
    __shared__ __align__(16) ull s_wg[32 * 16]; // [f][c] dup-packed, scale-folded
    __shared__ __align__(16) ull s_wr[32 * 8];
    __shared__ ull s_fg[32], s_fr[32];          // fused bias+shift, dup-packed

    PDL_WAIT();                    // g_sum/g_sumsq/g_mom must be final
    const int tid = threadIdx.x;
    const float inv = 1.0f / (float)NPIX;

    if (tid < 32) {                    // graph channels: accumulated sums
        float mean = g_sum[tid] * inv;
        float var  = g_sumsq[tid] * inv - mean * mean;
        float sc   = gamma[tid] * rsqrtf(var + BN_EPS);
        s_sc[tid] = sc;
        s_sh[tid] = beta[tid] - mean * sc;
    } else if (tid < 64) {             // grid channels: analytic from moments
        int j = tid - 32;
        float w[CI];
#pragma unroll
        for (int c = 0; c < CI; c++) w[c] = Wr[c * FH + j];
        float b = br[j];
        float sdot = 0.f;
#pragma unroll
        for (int c = 0; c < CI; c++) sdot += w[c] * g_mom[c];
        float qsum = 0.f;
        int k = 0;
#pragma unroll
        for (int c1 = 0; c1 < CI; c1++) {
            qsum += w[c1] * w[c1] * g_mom[CI + k]; k++;
#pragma unroll
            for (int c2 = c1 + 1; c2 < CI; c2++) {
                qsum += 2.f * w[c1] * w[c2] * g_mom[CI + k]; k++;
            }
        }
        float sum_x = sdot + (float)NPIX * b;
        float sumsq = qsum + 2.f * b * sdot + (float)NPIX * b * b;
        float mean = sum_x * inv;
        float var  = sumsq * inv - mean * mean;
        float sc   = gamma[tid] * rsqrtf(var + BN_EPS);
        s_sc[tid] = sc;
        s_sh[tid] = beta[tid] - mean * sc;
    }
    __syncthreads();

    {
#pragma unroll
        for (int k = 0; k < 2; k++) {            // 512 graph weight entries
            int e = tid + k * 256;
            int f = e >> 4, c = e & 15;
            float w = Wg[c * FH + f] * s_sc[f];
            PACK2(s_wg[e], w, w);
        }
        {                                         // 256 grid weight entries
            int f = tid >> 3, c = tid & 7;
            float w = Wr[c * FH + f] * s_sc[32 + f];
            PACK2(s_wr[tid], w, w);
        }
        if (tid < 32) {
            float v = bg[tid] * s_sc[tid] + s_sh[tid];
            PACK2(s_fg[tid], v, v);
        } else if (tid < 64) {
            int f = tid - 32;
            float v = br[f] * s_sc[32 + f] + s_sh[32 + f];
            PACK2(s_fr[f], v, v);
        }
    }
    __syncthreads();

    const int P  = blockIdx.x * NORM_TILE + tid * PXT;   // first of 4 pixels
    const int bt = P >> 14;
    const int hw = P & (HW - 1);
    float* outp = out + (size_t)bt * F_ * HW + hw;

    // ---- graph half: 16 channels x 4 px as pixel-pair packs ----
    {
        ull a01[CG], a23[CG];
        const float4* ip = (const float4*)&g_interp[(size_t)P * CG];
#pragma unroll
        for (int k = 0; k < 4; k++) {
            float4 v0 = __ldcs(&ip[k]);        // px0, channels 4k..4k+3
            float4 v1 = __ldcs(&ip[4 + k]);    // px1
            float4 v2 = __ldcs(&ip[8 + k]);    // px2
            float4 v3 = __ldcs(&ip[12 + k]);   // px3
            PACK2(a01[4*k+0], v0.x, v1.x); PACK2(a23[4*k+0], v2.x, v3.x);
            PACK2(a01[4*k+1], v0.y, v1.y); PACK2(a23[4*k+1], v2.y, v3.y);
            PACK2(a01[4*k+2], v0.z, v1.z); PACK2(a23[4*k+2], v2.z, v3.z);
            PACK2(a01[4*k+3], v0.w, v1.w); PACK2(a23[4*k+3], v2.w, v3.w);
        }

#pragma unroll 4
        for (int f = 0; f < 32; f++) {
            ull acc01 = s_fg[f], acc23 = s_fg[f];
            const ulonglong2* wrow = (const ulonglong2*)&s_wg[f * 16];
#pragma unroll
            for (int cc = 0; cc < 8; cc++) {
                ulonglong2 w = wrow[cc];          // uniform -> broadcast
                FMA2(acc01, a01[2*cc],   w.x, acc01);
                FMA2(acc23, a23[2*cc],   w.x, acc23);
                FMA2(acc01, a01[2*cc+1], w.y, acc01);
                FMA2(acc23, a23[2*cc+1], w.y, acc23);
            }
            float4 o;
            UNPACK2(o.x, o.y, acc01);
            UNPACK2(o.z, o.w, acc23);
            __stcs((float4*)&outp[(size_t)f * HW], o);   // coalesced STG.128
        }
    }

    // ---- grid half: 8 channels x 4 px ----
    {
        ull g01[CI], g23[CI];
        const float* gp = &grid_data[(size_t)bt * CI * HW + hw];
#pragma unroll
        for (int c = 0; c < CI; c++) {
            float4 v = __ldcs((const float4*)&gp[(size_t)c * HW]);
            PACK2(g01[c], v.x, v.y);
            PACK2(g23[c], v.z, v.w);
        }

#pragma unroll 4
        for (int f = 0; f < 32; f++) {
            ull acc01 = s_fr[f], acc23 = s_fr[f];
            const ulonglong2* wrow = (const ulonglong2*)&s_wr[f * 8];
#pragma unroll
            for (int cc = 0; cc < 4; cc++) {
                ulonglong2 w = wrow[cc];
                FMA2(acc01, g01[2*cc],   w.x, acc01);
                FMA2(acc23, g23[2*cc],   w.x, acc23);
                FMA2(acc01, g01[2*cc+1], w.y, acc01);
                FMA2(acc23, g23[2*cc+1], w.y, acc23);
            }
            float4 o;
            UNPACK2(o.x, o.y, acc01);
            UNPACK2(o.z, o.w, acc23);
            __stcs((float4*)&outp[(size_t)(32 + f) * HW], o);
        }
    }
}

extern "C" void kernel_launch(void* const* d_in, const int* in_sizes, int n_in,
                              void* d_out, int out_size) {
    (void)in_sizes; (void)n_in; (void)out_size;
    const float* graph     = (const float*)d_in[0];
    const float* grid_data = (const float*)d_in[1];
    const float* coords    = (const float*)d_in[2];
    const float* Wg        = (const float*)d_in[5];
    const float* bg        = (const float*)d_in[6];
    const float* Wr        = (const float*)d_in[7];
    const float* br        = (const float*)d_in[8];
    const float* gamma     = (const float*)d_in[9];
    const float* beta      = (const float*)d_in[10];
    float* out = (float*)d_out;

    // PDL launch attribute: allows each kernel to be launched while its
    // stream predecessor is still running (released by griddepcontrol).
    cudaLaunchAttribute pdl[1];
    pdl[0].id = cudaLaunchAttributeProgrammaticStreamSerialization;
    pdl[0].val.programmaticStreamSerializationAllowed = 1;

    {   // k_zero — no predecessor dependency needed
        cudaLaunchConfig_t cfg = {};
        cfg.gridDim = dim3(2048); cfg.blockDim = dim3(256); cfg.stream = 0;
        cudaLaunchKernelEx(&cfg, k_zero);
    }
    {   // k_scatter — PDL on k_zero
        cudaLaunchConfig_t cfg = {};
        cfg.gridDim = dim3(SCB + GMB); cfg.blockDim = dim3(256); cfg.stream = 0;
        cfg.attrs = pdl; cfg.numAttrs = 1;
        cudaLaunchKernelEx(&cfg, k_scatter, graph, coords, grid_data);
    }
    {   // k_stats — PDL on k_scatter
        cudaLaunchConfig_t cfg = {};
        cfg.gridDim = dim3(NSTAT); cfg.blockDim = dim3(256); cfg.stream = 0;
        cfg.attrs = pdl; cfg.numAttrs = 1;
        cudaLaunchKernelEx(&cfg, k_stats, Wg, bg);
    }
    {   // k_norm — PDL on k_stats
        cudaLaunchConfig_t cfg = {};
        cfg.gridDim = dim3(NNORM); cfg.blockDim = dim3(NORM_TPB); cfg.stream = 0;
        cfg.attrs = pdl; cfg.numAttrs = 1;
        cudaLaunchKernelEx(&cfg, k_norm, grid_data, Wg, bg, Wr, br,
                           gamma, beta, out);
    }
}